// round 15
// baseline (speedup 1.0000x reference)
#include <cuda_runtime.h>
#include <cuda_bf16.h>
#include <cstdint>

// Holt-Winters additive triple smoothing (gamma unused; season static).
// Reference step (t>=1), carried as v = (f, tr) with f = smooth+trend:
//   e  = y - (sea + f);  tn = tr + ab*e;  fn = f + al*e + tn;  out = fn + sea
// This is affine with CONSTANT matrix M: v' = M v + (y-sea)*[c2, ab]^T,
//   c2 = al+ab,  M = [[1-c2, 1], [-ab, 1]].
// => blocked-scan time parallelism: each 32-step chunk scanned locally with
// v0=0 (parallel), then out_t += A11(dt)*f0 + A12(dt)*tr0 with A = M^dt.
// Chunk 0 uses the exact initial state (t=0: out=y0+init_trend; f=y0+tr).
//
// R14: block = 16 rows x T=512 resident in one in-place smem buffer
// (33KB), 256 threads = (row, chunk). 4096 blocks -> 48 warps/SM (vs 7).
// Loads: 16 x 2KB cp.async.bulk per block (rows are contiguous!) -> LSU
// staging cost collapses ~64x vs per-chunk LDGSTS (R13's real binder).

constexpr int RB      = 16;    // rows per block
constexpr int NCH     = 16;    // chunks (T/32)
constexpr int C       = 32;    // steps per chunk
constexpr int THREADS = 256;   // RB * NCH
constexpr int STRIDE  = 516;   // smem row stride in floats (16B-mult, padded)

__device__ __forceinline__ uint32_t smem_u32(const void* p) {
    return (uint32_t)__cvta_generic_to_shared(p);
}

__device__ __forceinline__ void mbar_init(uint32_t mbar, uint32_t count) {
    asm volatile("mbarrier.init.shared.b64 [%0], %1;" :: "r"(mbar), "r"(count) : "memory");
}
__device__ __forceinline__ void mbar_expect_tx(uint32_t mbar, uint32_t bytes) {
    asm volatile("mbarrier.arrive.expect_tx.shared.b64 _, [%0], %1;"
                 :: "r"(mbar), "r"(bytes) : "memory");
}
__device__ __forceinline__ void mbar_wait(uint32_t mbar, uint32_t parity) {
    asm volatile(
        "{\n\t.reg .pred P;\n"
        "W%=:\n\t"
        "mbarrier.try_wait.parity.shared.b64 P, [%0], %1;\n\t"
        "@P bra D%=;\n\t"
        "bra W%=;\n"
        "D%=:\n\t}"
        :: "r"(mbar), "r"(parity) : "memory");
}
__device__ __forceinline__ void bulk_ld(uint32_t dst, const void* src,
                                        uint32_t bytes, uint32_t mbar) {
    asm volatile(
        "cp.async.bulk.shared::cluster.global.mbarrier::complete_tx::bytes "
        "[%0], [%1], %2, [%3];"
        :: "r"(dst), "l"(src), "r"(bytes), "r"(mbar) : "memory");
}

__device__ __forceinline__ float hw_step_f(float y, float sea,
                                           float& f, float& tr,
                                           float al, float ab)
{
    float e  = y - (sea + f);
    float tn = fmaf(ab, e, tr);
    float fn = fmaf(al, e, f) + tn;
    tr = tn;
    f  = fn;
    return fn + sea;
}

__global__ __launch_bounds__(THREADS, 6)
void hw_kernel(const float* __restrict__ series,
               const int*   __restrict__ shifts,
               const float* __restrict__ alpha_p,
               const float* __restrict__ beta_p,
               const float* __restrict__ season_g,
               const float* __restrict__ init_trend_p,
               float* __restrict__ out,
               int T)
{
    __shared__ float    s_buf[RB * STRIDE];   // 33024 B, in-place y -> out
    __shared__ float    s_season[12];
    __shared__ float2   s_carry[RB * NCH];    // local end carries (f~, tr~)
    __shared__ float2   s_v0[RB * NCH];       // true chunk-start carries
    __shared__ float2   s_A[C];               // s_A[i] = row0 of M^(i+1)
    __shared__ float4   s_M32;                // full M^32
    __shared__ uint64_t s_mbar;

    const int tid  = threadIdx.x;
    const int r    = tid & (RB - 1);
    const int c    = tid >> 4;
    const int row0 = blockIdx.x * RB;

    const float alpha      = *alpha_p;
    const float beta       = *beta_p;
    const float init_trend = *init_trend_p;
    const float ab = alpha * beta;
    const float c2 = alpha + ab;

    const uint32_t mbar = smem_u32(&s_mbar);

    if (tid == 0) mbar_init(mbar, 1);
    if (tid < 12) s_season[tid] = season_g[tid];
    __syncthreads();                  // mbar init + season visible

    if (tid == 0) {
        // launch all 16 row loads (contiguous 2KB each)
        mbar_expect_tx(mbar, RB * (uint32_t)(T * 4));
        for (int rr = 0; rr < RB; ++rr)
            bulk_ld(smem_u32(&s_buf[rr * STRIDE]),
                    series + (size_t)(row0 + rr) * T, T * 4, mbar);
        // build A(dt) = M^dt for dt=1..32 (row 0) and full M^32
        float p11 = 1.0f - c2, p12 = 1.0f, p21 = -ab, p22 = 1.0f;  // M^1
        s_A[0] = make_float2(p11, p12);
        for (int k = 1; k < C; ++k) {
            float n11 = (1.0f - c2) * p11 + p21;
            float n12 = (1.0f - c2) * p12 + p22;
            float n21 = -ab * p11 + p21;
            float n22 = -ab * p12 + p22;
            p11 = n11; p12 = n12; p21 = n21; p22 = n22;
            s_A[k] = make_float2(p11, p12);
        }
        s_M32 = make_float4(p11, p12, p21, p22);
    }

    mbar_wait(mbar, 0);               // tile landed, visible to all threads

    // ---- pass A: local scan of chunk c on row r (in place) --------------
    {
        const int shift = shifts[row0 + r];
        float* rowp = s_buf + r * STRIDE + c * C;
        float f, tr;
        int j;                         // season index (t - shift) mod 12

        if (c == 0) {
            j = (1 - shift) % 12; if (j < 0) j += 12;
            float4 y = *(float4*)rowp;
            f  = y.x + init_trend;     // state after t=0
            tr = init_trend;
            float4 o;
            o.x = f;                   // out[0] = y0 + init_trend
            float sea;
            sea = s_season[j]; j = (j + 1 == 12) ? 0 : j + 1;
            o.y = hw_step_f(y.y, sea, f, tr, alpha, ab);
            sea = s_season[j]; j = (j + 1 == 12) ? 0 : j + 1;
            o.z = hw_step_f(y.z, sea, f, tr, alpha, ab);
            sea = s_season[j]; j = (j + 1 == 12) ? 0 : j + 1;
            o.w = hw_step_f(y.w, sea, f, tr, alpha, ab);
            *(float4*)rowp = o;
            #pragma unroll
            for (int g = 1; g < C / 4; ++g) {
                float4 yy = *((float4*)rowp + g);
                float4 oo;
                sea = s_season[j]; j = (j + 1 == 12) ? 0 : j + 1;
                oo.x = hw_step_f(yy.x, sea, f, tr, alpha, ab);
                sea = s_season[j]; j = (j + 1 == 12) ? 0 : j + 1;
                oo.y = hw_step_f(yy.y, sea, f, tr, alpha, ab);
                sea = s_season[j]; j = (j + 1 == 12) ? 0 : j + 1;
                oo.z = hw_step_f(yy.z, sea, f, tr, alpha, ab);
                sea = s_season[j]; j = (j + 1 == 12) ? 0 : j + 1;
                oo.w = hw_step_f(yy.w, sea, f, tr, alpha, ab);
                *((float4*)rowp + g) = oo;
            }
        } else {
            int t0 = c * C;
            j = (t0 - shift) % 12; if (j < 0) j += 12;
            f = 0.0f; tr = 0.0f;       // local scan, zero carry-in
            #pragma unroll
            for (int g = 0; g < C / 4; ++g) {
                float4 yy = *((float4*)rowp + g);
                float4 oo;
                float sea;
                sea = s_season[j]; j = (j + 1 == 12) ? 0 : j + 1;
                oo.x = hw_step_f(yy.x, sea, f, tr, alpha, ab);
                sea = s_season[j]; j = (j + 1 == 12) ? 0 : j + 1;
                oo.y = hw_step_f(yy.y, sea, f, tr, alpha, ab);
                sea = s_season[j]; j = (j + 1 == 12) ? 0 : j + 1;
                oo.z = hw_step_f(yy.z, sea, f, tr, alpha, ab);
                sea = s_season[j]; j = (j + 1 == 12) ? 0 : j + 1;
                oo.w = hw_step_f(yy.w, sea, f, tr, alpha, ab);
                *((float4*)rowp + g) = oo;
            }
        }
        s_carry[r * NCH + c] = make_float2(f, tr);
    }
    __syncthreads();

    // ---- carry propagation: one thread per row --------------------------
    if (tid < RB) {
        const int rr = tid;
        float4 M = s_M32;
        float2 v = s_carry[rr * NCH + 0];         // exact after chunk 0
        s_v0[rr * NCH + 0] = make_float2(0.0f, 0.0f);  // chunk 0: no fix-up
        #pragma unroll
        for (int cc = 1; cc < NCH; ++cc) {
            s_v0[rr * NCH + cc] = v;
            float2 lc = s_carry[rr * NCH + cc];
            float nf = fmaf(M.x, v.x, fmaf(M.y, v.y, lc.x));
            float nt = fmaf(M.z, v.x, fmaf(M.w, v.y, lc.y));
            v = make_float2(nf, nt);
        }
    }
    __syncthreads();

    // ---- fix-up + coalesced store ---------------------------------------
    {
        const int t4 = T >> 2;                    // 128 float4 per row
        float4* __restrict__ dstv = (float4*)out;
        #pragma unroll
        for (int k = 0; k < (RB * 128) / THREADS; ++k) {   // 8 iters
            int q  = k * THREADS + tid;
            int rr = q >> 7;
            int f4 = q & 127;
            float4 v4 = *(float4*)(s_buf + rr * STRIDE + f4 * 4);
            int cc = f4 >> 3;
            int i0 = (f4 & 7) * 4;                // in-chunk step index base
            float2 v0 = s_v0[rr * NCH + cc];
            float2 A0 = s_A[i0 + 0];
            float2 A1 = s_A[i0 + 1];
            float2 A2 = s_A[i0 + 2];
            float2 A3 = s_A[i0 + 3];
            v4.x = fmaf(A0.x, v0.x, fmaf(A0.y, v0.y, v4.x));
            v4.y = fmaf(A1.x, v0.x, fmaf(A1.y, v0.y, v4.y));
            v4.z = fmaf(A2.x, v0.x, fmaf(A2.y, v0.y, v4.z));
            v4.w = fmaf(A3.x, v0.x, fmaf(A3.y, v0.y, v4.w));
            dstv[(size_t)(row0 + rr) * t4 + f4] = v4;
        }
    }
}

// Generic fallback (shape-safe) for any B/T/slen — reference formulation.
__global__ __launch_bounds__(256)
void hw_kernel_generic(const float* __restrict__ series,
                       const int*   __restrict__ shifts,
                       const float* __restrict__ alpha_p,
                       const float* __restrict__ beta_p,
                       const float* __restrict__ season_g,
                       const float* __restrict__ init_trend_p,
                       float* __restrict__ out,
                       int B, int T, int slen)
{
    int row = blockIdx.x * blockDim.x + threadIdx.x;
    if (row >= B) return;
    const float alpha = *alpha_p, beta = *beta_p;
    const float oma = 1.0f - alpha, omb = 1.0f - beta;
    int shift = shifts[row];
    int idx = (1 - shift) % slen; if (idx < 0) idx += slen;
    const float* src = series + (size_t)row * T;
    float* dst = out + (size_t)row * T;
    float smooth = src[0], trend = *init_trend_p;
    dst[0] = smooth + trend;
    for (int t = 1; t < T; ++t) {
        float sea = season_g[idx];
        idx = (idx + 1 == slen) ? 0 : idx + 1;
        float sn = alpha * (src[t] - sea) + oma * (smooth + trend);
        float tn = beta * (sn - smooth) + omb * trend;
        dst[t] = sn + tn + sea;
        smooth = sn; trend = tn;
    }
}

extern "C" void kernel_launch(void* const* d_in, const int* in_sizes, int n_in,
                              void* d_out, int out_size)
{
    // 0: series f32 [B*T]   1: shifts i32 [B]   2: alpha   3: beta
    // 4: gamma (unused)     5: init_season [SLEN]   6: init_trend   7: n_preds
    const float* series     = (const float*)d_in[0];
    const int*   shifts     = (const int*)  d_in[1];
    const float* alpha_p    = (const float*)d_in[2];
    const float* beta_p     = (const float*)d_in[3];
    const float* season     = (const float*)d_in[5];
    const float* init_trend = (const float*)d_in[6];
    float* out = (float*)d_out;

    int B    = in_sizes[1];
    int T    = in_sizes[0] / B;      // 512
    int slen = in_sizes[5];          // 12

    if (slen == 12 && T == 512 && (B % RB) == 0) {
        int blocks = B / RB;         // 4096
        hw_kernel<<<blocks, THREADS>>>(series, shifts, alpha_p, beta_p,
                                       season, init_trend, out, T);
    } else {
        int threads = 256;
        int blocks  = (B + threads - 1) / threads;
        hw_kernel_generic<<<blocks, threads>>>(series, shifts, alpha_p, beta_p,
                                               season, init_trend, out,
                                               B, T, slen);
    }
}